// round 1
// baseline (speedup 1.0000x reference)
#include <cuda_runtime.h>
#include <cstdint>
#include <cstddef>

#define NUM_USERS 100000
#define NUM_ITEMS 50000
#define DIM 64
#define P_PATHS 3
#define BATCH 8192
#define EU (NUM_USERS * 16)   // 1,600,000 edges per user path
#define EI (NUM_ITEMS * 16)   //   800,000 edges per item path

// ---------------- device scratch (static globals: no allocation allowed) ----
__device__ float4 g_Su[(size_t)P_PATHS * NUM_USERS * (DIM / 4)];  // 76.8 MB
__device__ float4 g_Si[(size_t)P_PATHS * NUM_ITEMS * (DIM / 4)];  // 38.4 MB
__device__ unsigned char g_uflag[NUM_USERS];
__device__ unsigned char g_iflag[NUM_ITEMS];

// ---------------- kernel 1: clear flags ------------------------------------
__global__ void k_clear_flags() {
    int i = blockIdx.x * blockDim.x + threadIdx.x;
    if (i < NUM_USERS) g_uflag[i] = 0;
    if (i < NUM_ITEMS) g_iflag[i] = 0;
}

// ---------------- kernel 2: mark needed rows --------------------------------
__global__ void k_set_flags(const int* __restrict__ user_idx,
                            const int* __restrict__ item_idx,
                            const int* __restrict__ neg_idx) {
    int i = blockIdx.x * blockDim.x + threadIdx.x;
    if (i < BATCH)               g_uflag[user_idx[i]] = 1;
    else if (i < 2 * BATCH)      g_iflag[item_idx[i - BATCH]] = 1;
    else if (i < 3 * BATCH)      g_iflag[neg_idx[i - 2 * BATCH]] = 1;
}

// ---------------- kernel 3: zero only the flagged accumulator rows ----------
__global__ void k_zero_S() {
    int r = blockIdx.x * blockDim.x + threadIdx.x;
    const float4 z = make_float4(0.f, 0.f, 0.f, 0.f);
    if (r < NUM_USERS) {
        if (g_uflag[r]) {
            #pragma unroll
            for (int p = 0; p < P_PATHS; p++) {
                float4* dst = &g_Su[((size_t)p * NUM_USERS + r) * (DIM / 4)];
                #pragma unroll
                for (int k = 0; k < DIM / 4; k++) dst[k] = z;
            }
        }
    } else {
        int ri = r - NUM_USERS;
        if (ri < NUM_ITEMS && g_iflag[ri]) {
            #pragma unroll
            for (int p = 0; p < P_PATHS; p++) {
                float4* dst = &g_Si[((size_t)p * NUM_ITEMS + ri) * (DIM / 4)];
                #pragma unroll
                for (int k = 0; k < DIM / 4; k++) dst[k] = z;
            }
        }
    }
}

// ---------------- kernel 4/5: flag-filtered SpMM on raw table ---------------
// S[p*nn + row] += val * table[col]   for edges whose row is flagged.
// One thread per edge for the filter; flagged edges are processed warp-
// cooperatively (16 lanes, float4 gather + red.add.v4) via ballot loop.
__global__ void k_spmm(const int* __restrict__ rows,
                       const int* __restrict__ cols,
                       const float* __restrict__ vals,
                       const float4* __restrict__ table,
                       float4* __restrict__ S,
                       const unsigned char* __restrict__ flag,
                       int n_edges, int edges_per_path, int nn) {
    int e = blockIdx.x * blockDim.x + threadIdx.x;
    int lane = threadIdx.x & 31;
    bool act = false;
    int sIdx = 0, c = 0;
    float v = 0.f;
    if (e < n_edges) {
        int r = rows[e];
        if (flag[r]) {
            int p = e / edges_per_path;
            sIdx = p * nn + r;
            c = cols[e];
            v = vals[e];
            act = true;
        }
    }
    unsigned m = __ballot_sync(0xffffffffu, act);
    while (m) {
        int src = __ffs(m) - 1;
        m &= m - 1;
        int si   = __shfl_sync(0xffffffffu, sIdx, src);
        int cc   = __shfl_sync(0xffffffffu, c, src);
        float vv = __shfl_sync(0xffffffffu, v, src);
        if (lane < 16) {
            float4 t = __ldg(&table[(size_t)cc * (DIM / 4) + lane]);
            float4* dst = &S[(size_t)si * (DIM / 4) + lane];
            asm volatile("red.global.add.v4.f32 [%0], {%1,%2,%3,%4};"
                         :: "l"(dst), "f"(vv * t.x), "f"(vv * t.y),
                            "f"(vv * t.z), "f"(vv * t.w)
                         : "memory");
        }
    }
}

// ---------------- kernel 6: gather + per-path 64x64 matvec + relu fusion ----
// out[g] = relu( sum_p wb[p] * relu( S[p][idx[g]] @ W[p] ) )
// One warp handles R=4 consecutive output rows (branch is uniform per warp
// since all section boundaries are multiples of 4).
#define R_ROWS 4
__global__ void k_emb(const float* __restrict__ W_u,
                      const float* __restrict__ W_i,
                      const float* __restrict__ wb1,
                      const float* __restrict__ wb2,
                      const int* __restrict__ user_idx,
                      const int* __restrict__ item_idx,
                      const int* __restrict__ neg_idx,
                      float* __restrict__ out) {
    int w = (blockIdx.x * blockDim.x + threadIdx.x) >> 5;
    int lane = threadIdx.x & 31;
    int base = w * R_ROWS;
    if (base >= 3 * BATCH) return;

    bool isUser = base < BATCH;
    const float* S  = isUser ? (const float*)g_Su : (const float*)g_Si;
    const float* W  = isUser ? W_u : W_i;
    const float* wb = isUser ? wb1 : wb2;
    int nn = isUser ? NUM_USERS : NUM_ITEMS;

    int rows[R_ROWS];
    #pragma unroll
    for (int j = 0; j < R_ROWS; j++) {
        int gi = base + j;
        if (gi < BATCH)            rows[j] = user_idx[gi];
        else if (gi < 2 * BATCH)   rows[j] = item_idx[gi - BATCH];
        else                       rows[j] = neg_idx[gi - 2 * BATCH];
    }

    float acc0[R_ROWS], acc1[R_ROWS];
    #pragma unroll
    for (int j = 0; j < R_ROWS; j++) { acc0[j] = 0.f; acc1[j] = 0.f; }

    for (int p = 0; p < P_PATHS; p++) {
        float s0[R_ROWS], s1[R_ROWS];
        #pragma unroll
        for (int j = 0; j < R_ROWS; j++) {
            const float* Sr = S + ((size_t)p * nn + rows[j]) * DIM;
            s0[j] = Sr[lane];
            s1[j] = Sr[lane + 32];
        }
        float y0[R_ROWS], y1[R_ROWS];
        #pragma unroll
        for (int j = 0; j < R_ROWS; j++) { y0[j] = 0.f; y1[j] = 0.f; }

        const float* Wp = W + p * DIM * DIM;
        #pragma unroll 8
        for (int d = 0; d < DIM; d++) {
            float wlo = __ldg(&Wp[d * DIM + lane]);
            float whi = __ldg(&Wp[d * DIM + lane + 32]);
            #pragma unroll
            for (int j = 0; j < R_ROWS; j++) {
                float sv = __shfl_sync(0xffffffffu,
                                       (d < 32) ? s0[j] : s1[j], d & 31);
                y0[j] += sv * wlo;
                y1[j] += sv * whi;
            }
        }
        float cwb = wb[p];
        #pragma unroll
        for (int j = 0; j < R_ROWS; j++) {
            acc0[j] += cwb * fmaxf(y0[j], 0.f);
            acc1[j] += cwb * fmaxf(y1[j], 0.f);
        }
    }
    #pragma unroll
    for (int j = 0; j < R_ROWS; j++) {
        out[(size_t)(base + j) * DIM + lane]      = fmaxf(acc0[j], 0.f);
        out[(size_t)(base + j) * DIM + lane + 32] = fmaxf(acc1[j], 0.f);
    }
}

// ---------------- launch ----------------------------------------------------
extern "C" void kernel_launch(void* const* d_in, const int* in_sizes, int n_in,
                              void* d_out, int out_size) {
    const float4* user_table = (const float4*)d_in[0];
    const float4* item_table = (const float4*)d_in[1];
    const float* W_u  = (const float*)d_in[2];
    const float* W_i  = (const float*)d_in[3];
    const float* wb1  = (const float*)d_in[4];
    const float* wb2  = (const float*)d_in[5];
    const float* user_vals = (const float*)d_in[6];
    const float* item_vals = (const float*)d_in[7];
    const int* user_rows = (const int*)d_in[8];
    const int* user_cols = (const int*)d_in[9];
    const int* item_rows = (const int*)d_in[10];
    const int* item_cols = (const int*)d_in[11];
    const int* user_idx = (const int*)d_in[12];
    const int* item_idx = (const int*)d_in[13];
    const int* neg_idx  = (const int*)d_in[14];
    float* out = (float*)d_out;

    float4* Su; cudaGetSymbolAddress((void**)&Su, g_Su);
    float4* Si; cudaGetSymbolAddress((void**)&Si, g_Si);
    unsigned char* uflag; cudaGetSymbolAddress((void**)&uflag, g_uflag);
    unsigned char* iflag; cudaGetSymbolAddress((void**)&iflag, g_iflag);

    k_clear_flags<<<(NUM_USERS + 255) / 256, 256>>>();
    k_set_flags<<<(3 * BATCH + 255) / 256, 256>>>(user_idx, item_idx, neg_idx);
    k_zero_S<<<(NUM_USERS + NUM_ITEMS + 255) / 256, 256>>>();

    int n_ue = P_PATHS * EU;
    int n_ie = P_PATHS * EI;
    k_spmm<<<(n_ue + 255) / 256, 256>>>(user_rows, user_cols, user_vals,
                                        user_table, Su, uflag,
                                        n_ue, EU, NUM_USERS);
    k_spmm<<<(n_ie + 255) / 256, 256>>>(item_rows, item_cols, item_vals,
                                        item_table, Si, iflag,
                                        n_ie, EI, NUM_ITEMS);

    int total_rows = 3 * BATCH;                 // 24576
    int warps = total_rows / R_ROWS;            // 6144
    k_emb<<<(warps * 32 + 255) / 256, 256>>>(W_u, W_i, wb1, wb2,
                                             user_idx, item_idx, neg_idx, out);
}

// round 2
// speedup vs baseline: 1.6026x; 1.6026x over previous
#include <cuda_runtime.h>
#include <cstdint>
#include <cstddef>

#define NUM_USERS 100000
#define NUM_ITEMS 50000
#define DIM 64
#define P_PATHS 3
#define BATCH 8192
#define EU 1600000            // edges per user path
#define EI 800000             // edges per item path
#define UQ_PER_PATH (EU / 4)  // 400000 int4-quads per user path
#define IQ_PER_PATH (EI / 4)  // 200000 int4-quads per item path
#define UQ (P_PATHS * UQ_PER_PATH)  // 1,200,000
#define IQ (P_PATHS * IQ_PER_PATH)  //   600,000
#define NBU ((UQ + 255) / 256)      // 4688 blocks (user section)
#define NBI ((IQ + 255) / 256)      // 2344 blocks (item section)
#define UMASK_WORDS ((NUM_USERS + 31) / 32)  // 3125
#define IMASK_WORDS ((NUM_ITEMS + 31) / 32)  // 1563

// ---------------- device scratch (static globals: no allocation allowed) ----
__device__ float4 g_Su[(size_t)P_PATHS * NUM_USERS * (DIM / 4)];  // 76.8 MB
__device__ float4 g_Si[(size_t)P_PATHS * NUM_ITEMS * (DIM / 4)];  // 38.4 MB
__device__ unsigned g_umask[UMASK_WORDS];  // 12.5 KB  (L1-resident)
__device__ unsigned g_imask[IMASK_WORDS];  //  6.3 KB  (L1-resident)

// ---------------- kernel 1: clear bitmasks ----------------------------------
__global__ void k_clear() {
    int i = blockIdx.x * blockDim.x + threadIdx.x;
    if (i < UMASK_WORDS) g_umask[i] = 0;
    else if (i < UMASK_WORDS + IMASK_WORDS) g_imask[i - UMASK_WORDS] = 0;
}

// ---------------- kernel 2: set flag bits + zero the needed S rows ----------
// Each batch element marks its row in the bitmask and zeros that row's
// accumulators across all 3 paths. Duplicate rows write zero concurrently,
// which is benign.
__global__ void k_prep(const int* __restrict__ user_idx,
                       const int* __restrict__ item_idx,
                       const int* __restrict__ neg_idx) {
    int i = blockIdx.x * blockDim.x + threadIdx.x;
    if (i >= 3 * BATCH) return;
    int r, nn;
    float4* S;
    if (i < BATCH) {
        r = user_idx[i];
        atomicOr(&g_umask[r >> 5], 1u << (r & 31));
        S = g_Su; nn = NUM_USERS;
    } else {
        r = (i < 2 * BATCH) ? item_idx[i - BATCH] : neg_idx[i - 2 * BATCH];
        atomicOr(&g_imask[r >> 5], 1u << (r & 31));
        S = g_Si; nn = NUM_ITEMS;
    }
    const float4 z = make_float4(0.f, 0.f, 0.f, 0.f);
    #pragma unroll
    for (int p = 0; p < P_PATHS; p++) {
        float4* dst = S + ((size_t)p * nn + r) * (DIM / 4);
        #pragma unroll
        for (int k = 0; k < DIM / 4; k++) dst[k] = z;
    }
}

// ---------------- kernel 3: fused flag-filtered SpMM ------------------------
// Grid split: first NBU blocks handle user edges, rest handle item edges.
// Each thread owns 4 consecutive edges (int4/float4 vector loads). Flagged
// edges are warp-compacted into smem, then processed two-at-a-time with
// 16 lanes per edge: float4 gather from the table + red.global.add.v4.
__global__ void __launch_bounds__(256)
k_spmm(const int4* __restrict__ urows, const int4* __restrict__ ucols,
       const float4* __restrict__ uvals, const float4* __restrict__ utab,
       const int4* __restrict__ irows, const int4* __restrict__ icols,
       const float4* __restrict__ ivals, const float4* __restrict__ itab) {
    __shared__ int   s_si[8][136];
    __shared__ int   s_c [8][136];
    __shared__ float s_v [8][136];

    int tid = threadIdx.x;
    int wid = tid >> 5;
    int lane = tid & 31;

    const int4* rows; const int4* cols; const float4* vals; const float4* tab;
    float4* S; const unsigned* mask;
    int nq, qpp, nn, gq;
    if (blockIdx.x < NBU) {
        rows = urows; cols = ucols; vals = uvals; tab = utab;
        S = g_Su; mask = g_umask;
        nq = UQ; qpp = UQ_PER_PATH; nn = NUM_USERS;
        gq = blockIdx.x * 256 + tid;
    } else {
        rows = irows; cols = icols; vals = ivals; tab = itab;
        S = g_Si; mask = g_imask;
        nq = IQ; qpp = IQ_PER_PATH; nn = NUM_ITEMS;
        gq = (blockIdx.x - NBU) * 256 + tid;
    }

    bool inb = gq < nq;
    int4 rr = make_int4(0, 0, 0, 0), cc = make_int4(0, 0, 0, 0);
    float4 vv = make_float4(0.f, 0.f, 0.f, 0.f);
    int pbase = 0;
    if (inb) {
        rr = __ldg(&rows[gq]);
        cc = __ldg(&cols[gq]);
        vv = __ldg(&vals[gq]);
        pbase = (gq / qpp) * nn;  // path is constant within an int4 quad
    }

    int r4[4] = {rr.x, rr.y, rr.z, rr.w};
    int c4[4] = {cc.x, cc.y, cc.z, cc.w};
    float v4[4] = {vv.x, vv.y, vv.z, vv.w};

    int cnt = 0;
    #pragma unroll
    for (int s = 0; s < 4; s++) {
        int r = r4[s];
        bool act = inb && ((mask[r >> 5] >> (r & 31)) & 1u);
        unsigned m = __ballot_sync(0xffffffffu, act);
        if (act) {
            int pos = cnt + __popc(m & ((1u << lane) - 1u));
            s_si[wid][pos] = pbase + r;
            s_c [wid][pos] = c4[s];
            s_v [wid][pos] = v4[s];
        }
        cnt += __popc(m);
    }
    __syncwarp();

    int half = lane >> 4;
    int l16 = lane & 15;
    for (int k0 = 0; k0 < cnt; k0 += 2) {
        int k = k0 + half;
        if (k < cnt) {
            int si = s_si[wid][k];
            int c  = s_c [wid][k];
            float v = s_v[wid][k];
            float4 t = __ldg(&tab[(size_t)c * (DIM / 4) + l16]);
            float4* dst = &S[(size_t)si * (DIM / 4) + l16];
            asm volatile("red.global.add.v4.f32 [%0], {%1,%2,%3,%4};"
                         :: "l"(dst), "f"(v * t.x), "f"(v * t.y),
                            "f"(v * t.z), "f"(v * t.w)
                         : "memory");
        }
    }
}

// ---------------- kernel 4: gather + per-path 64x64 matvec + relu fusion ----
// Block = 8 warps = 32 consecutive output rows (section boundaries are
// multiples of 32, so the user/item branch is uniform per block).
// W for the relevant branch is staged in 48 KB smem; the inner loop is
// LDS + shfl + FFMA only.
#define R_ROWS 4
__global__ void __launch_bounds__(256)
k_emb(const float4* __restrict__ W_u, const float4* __restrict__ W_i,
      const float* __restrict__ wb1, const float* __restrict__ wb2,
      const int* __restrict__ user_idx, const int* __restrict__ item_idx,
      const int* __restrict__ neg_idx, float* __restrict__ out) {
    __shared__ float sW[P_PATHS * DIM * DIM];  // 48 KB

    int tid = threadIdx.x;
    int wid = tid >> 5;
    int lane = tid & 31;
    int block_base = blockIdx.x * 32;

    bool isUser = block_base < BATCH;
    const float4* Wsrc = isUser ? W_u : W_i;
    const float* wb = isUser ? wb1 : wb2;
    const float* S = isUser ? (const float*)g_Su : (const float*)g_Si;
    int nn = isUser ? NUM_USERS : NUM_ITEMS;

    #pragma unroll
    for (int i = 0; i < (P_PATHS * DIM * DIM / 4) / 256; i++)
        ((float4*)sW)[i * 256 + tid] = __ldg(&Wsrc[i * 256 + tid]);
    __syncthreads();

    int base = block_base + wid * R_ROWS;
    int rows[R_ROWS];
    #pragma unroll
    for (int j = 0; j < R_ROWS; j++) {
        int gi = base + j;
        if (gi < BATCH)          rows[j] = user_idx[gi];
        else if (gi < 2 * BATCH) rows[j] = item_idx[gi - BATCH];
        else                     rows[j] = neg_idx[gi - 2 * BATCH];
    }

    float acc0[R_ROWS], acc1[R_ROWS];
    #pragma unroll
    for (int j = 0; j < R_ROWS; j++) { acc0[j] = 0.f; acc1[j] = 0.f; }

    #pragma unroll
    for (int p = 0; p < P_PATHS; p++) {
        float s0[R_ROWS], s1[R_ROWS];
        #pragma unroll
        for (int j = 0; j < R_ROWS; j++) {
            const float* Sr = S + ((size_t)p * nn + rows[j]) * DIM;
            s0[j] = __ldg(&Sr[lane]);
            s1[j] = __ldg(&Sr[lane + 32]);
        }
        float y0[R_ROWS], y1[R_ROWS];
        #pragma unroll
        for (int j = 0; j < R_ROWS; j++) { y0[j] = 0.f; y1[j] = 0.f; }

        const float* Wp = sW + p * DIM * DIM;
        #pragma unroll 8
        for (int d = 0; d < DIM; d++) {
            float wlo = Wp[d * DIM + lane];
            float whi = Wp[d * DIM + lane + 32];
            #pragma unroll
            for (int j = 0; j < R_ROWS; j++) {
                float sv = __shfl_sync(0xffffffffu,
                                       (d < 32) ? s0[j] : s1[j], d & 31);
                y0[j] += sv * wlo;
                y1[j] += sv * whi;
            }
        }
        float cwb = __ldg(&wb[p]);
        #pragma unroll
        for (int j = 0; j < R_ROWS; j++) {
            acc0[j] += cwb * fmaxf(y0[j], 0.f);
            acc1[j] += cwb * fmaxf(y1[j], 0.f);
        }
    }
    #pragma unroll
    for (int j = 0; j < R_ROWS; j++) {
        out[(size_t)(base + j) * DIM + lane]      = fmaxf(acc0[j], 0.f);
        out[(size_t)(base + j) * DIM + lane + 32] = fmaxf(acc1[j], 0.f);
    }
}

// ---------------- launch ----------------------------------------------------
extern "C" void kernel_launch(void* const* d_in, const int* in_sizes, int n_in,
                              void* d_out, int out_size) {
    const float4* user_table = (const float4*)d_in[0];
    const float4* item_table = (const float4*)d_in[1];
    const float4* W_u = (const float4*)d_in[2];
    const float4* W_i = (const float4*)d_in[3];
    const float* wb1 = (const float*)d_in[4];
    const float* wb2 = (const float*)d_in[5];
    const float4* user_vals = (const float4*)d_in[6];
    const float4* item_vals = (const float4*)d_in[7];
    const int4* user_rows = (const int4*)d_in[8];
    const int4* user_cols = (const int4*)d_in[9];
    const int4* item_rows = (const int4*)d_in[10];
    const int4* item_cols = (const int4*)d_in[11];
    const int* user_idx = (const int*)d_in[12];
    const int* item_idx = (const int*)d_in[13];
    const int* neg_idx  = (const int*)d_in[14];
    float* out = (float*)d_out;

    k_clear<<<(UMASK_WORDS + IMASK_WORDS + 255) / 256, 256>>>();
    k_prep<<<(3 * BATCH + 255) / 256, 256>>>(user_idx, item_idx, neg_idx);
    k_spmm<<<NBU + NBI, 256>>>(user_rows, user_cols, user_vals, user_table,
                               item_rows, item_cols, item_vals, item_table);
    k_emb<<<(3 * BATCH) / 32, 256>>>(W_u, W_i, wb1, wb2,
                                     user_idx, item_idx, neg_idx, out);
}